// round 8
// baseline (speedup 1.0000x reference)
#include <cuda_runtime.h>
#include <cuda_fp16.h>
#include <cstdint>

#define NBLK   128
#define NTHR   128
#define TSTEPS 512
#define OUTN   (512*128*512)

// ---- lstm smem byte offsets ------------------------------------------------
#define SM_BIAS 0         // 32 f32
#define SM_ZSH  128       // 16*132*4 = 8448
#define SM_W    8576      // B frags: [l*2+half][64 sg][2 nt][32 lane]*8B = 131072
#define SM_A    139648    // 4 bufs * 16KB
#define SM_TOT  205184

// ---- x0gemm smem -----------------------------------------------------------
#define XW_BYTES 131072
#define X0_TOT   (XW_BYTES + 65536)

// ---- persistent state ------------------------------------------------------
__device__ __align__(16) __half g_x[(size_t)TSTEPS*128*512];
__device__ __align__(16) float  g_z0x[(size_t)TSTEPS*2048*128];   // [t][c_g][n]
__device__ __align__(16) __half g_hst[2][2][128*512];   // [layer][pingpong]
__device__ __align__(16) __half g_mid[2][128*512];      // [pingpong]
__device__ unsigned g_bar_count = 0;
__device__ volatile unsigned g_bar_gen = 0;
__device__ unsigned g_cntA = 0, g_cntB = 0;
__device__ volatile unsigned g_genA = 0, g_genB = 0;

// ---- init grid barrier (replay-safe relative-gen) ---------------------------
__device__ __forceinline__ void grid_barrier_init() {
    __syncthreads();
    if (threadIdx.x == 0) {
        __threadfence();
        unsigned gen = g_bar_gen;
        if (atomicAdd(&g_bar_count, 1u) == NBLK - 1) {
            g_bar_count = 0;
            __threadfence();
            g_bar_gen = gen + 1;
        } else {
            while (g_bar_gen == gen) { __nanosleep(20); }
        }
        __threadfence();
    }
    __syncthreads();
}

// split barrier ops (tid0-only callers)
__device__ __forceinline__ void bar_arrive(unsigned* cnt, volatile unsigned* gen) {
    __threadfence();
    if (atomicAdd(cnt, 1u) == NBLK - 1) {
        *cnt = 0;
        __threadfence();
        *gen = *gen + 1;
    }
}
__device__ __forceinline__ void bar_wait(volatile unsigned* gen, unsigned target) {
    while ((int)(*gen - target) < 0) { }
    __threadfence();
}

// ---- asm helpers -----------------------------------------------------------
__device__ __forceinline__ void cp16(uint32_t s, const void* g) {
    asm volatile("cp.async.cg.shared.global [%0], [%1], 16;" :: "r"(s), "l"(g));
}
__device__ __forceinline__ void cp_commit() { asm volatile("cp.async.commit_group;"); }
template<int N> __device__ __forceinline__ void cp_wait() {
    asm volatile("cp.async.wait_group %0;" :: "n"(N));
}
__device__ __forceinline__ void ldm4(uint32_t (&a)[4], uint32_t addr) {
    asm volatile("ldmatrix.sync.aligned.m8n8.x4.shared.b16 {%0,%1,%2,%3}, [%4];"
                 : "=r"(a[0]), "=r"(a[1]), "=r"(a[2]), "=r"(a[3]) : "r"(addr));
}
__device__ __forceinline__ void mma(float (&d)[4], const uint32_t (&a)[4],
                                    uint32_t b0, uint32_t b1) {
    asm volatile("mma.sync.aligned.m16n8k16.row.col.f32.f16.f16.f32 "
        "{%0,%1,%2,%3}, {%4,%5,%6,%7}, {%8,%9}, {%0,%1,%2,%3};"
        : "+f"(d[0]), "+f"(d[1]), "+f"(d[2]), "+f"(d[3])
        : "r"(a[0]), "r"(a[1]), "r"(a[2]), "r"(a[3]), "r"(b0), "r"(b1));
}
__device__ __forceinline__ void stcg2(void* p, uint32_t a, uint32_t b) {
    asm volatile("st.global.cg.v2.b32 [%0], {%1,%2};" :: "l"(p), "r"(a), "r"(b));
}
__device__ __forceinline__ void stcg16(void* p, unsigned short v) {
    asm volatile("st.global.cg.u16 [%0], %1;" :: "l"(p), "h"(v));
}

__device__ __forceinline__ float sigm(float x) { return 1.0f / (1.0f + __expf(-x)); }

__device__ __forceinline__ void h2split(float v, unsigned short& hi, unsigned short& lo) {
    __half h = __float2half_rn(v);
    float r = v - __half2float(h);
    __half l2 = __float2half_rn(r);
    hi = __half_as_ushort(h);
    lo = __half_as_ushort(l2);
}

// ---- A staging, 4-warp version: warp w stages its 32-row band --------------
__device__ __forceinline__ void stage_w32(const __half* s0, const __half* s1,
                                          int c, uint32_t abase, int w, int lane) {
    const __half* p = (c < 8) ? s0 : s1;
    int coff = (c & 7) << 6;
    uint32_t dst = abase + (c & 3) * 16384;
    int rq = lane >> 3, cq = lane & 7;
#pragma unroll
    for (int jj = 0; jj < 8; ++jj) {
        int row = w * 32 + jj * 4 + rq;
        uint32_t d = dst + row * 128 + ((cq ^ (row & 7)) << 4);
        cp16(d, p + (size_t)row * 512 + coff + cq * 8);
    }
}
// ---- A staging, 8-warp version (x0gemm): warp w stages its 16-row band -----
__device__ __forceinline__ void stage_w16(const __half* s0,
                                          int c, uint32_t abase, int w, int lane) {
    int coff = (c & 7) << 6;
    uint32_t dst = abase + (c & 3) * 16384;
    int rq = lane >> 3, cq = lane & 7;
#pragma unroll
    for (int jj = 0; jj < 4; ++jj) {
        int row = w * 16 + jj * 4 + rq;
        uint32_t d = dst + row * 128 + ((cq ^ (row & 7)) << 4);
        cp16(d, s0 + (size_t)row * 512 + coff + cq * 8);
    }
}

// ---- per-chunk GEMM: 4 ks x (2 nt x 2 products) ----------------------------
__device__ __forceinline__ void chunk_mma(int l, int c, uint32_t abase,
                                          const uint2* bf, int w, int lane,
                                          float (&acc)[2][2][4]) {
    int sub = lane >> 3, lrow = lane & 7;
    uint32_t ab = abase + (c & 3) * 16384;
#pragma unroll
    for (int ks = 0; ks < 4; ++ks) {
        uint32_t Ah[2][4];
#pragma unroll
        for (int mt = 0; mt < 2; ++mt) {
            int r = w * 32 + mt * 16 + ((sub & 1) << 3) + lrow;
            uint32_t aoff = r * 128 + (((2 * ks + (sub >> 1)) ^ (r & 7)) << 4);
            ldm4(Ah[mt], ab + aoff);
        }
        int sg = c * 4 + ks;
        uint2 Bh0 = bf[(((l * 2 + 0) * 64 + sg) * 2 + 0) * 32 + lane];
        uint2 Bh1 = bf[(((l * 2 + 0) * 64 + sg) * 2 + 1) * 32 + lane];
        uint2 Bl0 = bf[(((l * 2 + 1) * 64 + sg) * 2 + 0) * 32 + lane];
        uint2 Bl1 = bf[(((l * 2 + 1) * 64 + sg) * 2 + 1) * 32 + lane];
#pragma unroll
        for (int mt = 0; mt < 2; ++mt) {
            mma(acc[mt][0], Ah[mt], Bh0.x, Bh0.y);
            mma(acc[mt][1], Ah[mt], Bh1.x, Bh1.y);
            mma(acc[mt][0], Ah[mt], Bl0.x, Bl0.y);
            mma(acc[mt][1], Ah[mt], Bl1.x, Bl1.y);
        }
    }
}

// ---- shared epilogue: z transpose + gates + state writes -------------------
__device__ __forceinline__ void epilogue(
    int l, int t, int blk, float (&acc)[2][2][4], const float* zreg,
    __half* hdst, __half* mdst, char* sm,
    float (&creg)[4], const float* __restrict__ masks, float* __restrict__ out)
{
    int tid = threadIdx.x, w = tid >> 5, lane = tid & 31;
    float* zsh = (float*)(sm + SM_ZSH);
#pragma unroll
    for (int mt = 0; mt < 2; ++mt)
#pragma unroll
        for (int nt = 0; nt < 2; ++nt) {
            int m0 = w * 32 + mt * 16 + (lane >> 2);
            int n0 = nt * 8 + (lane & 3) * 2;
            zsh[n0 * 132 + m0]           = acc[mt][nt][0];
            zsh[(n0 + 1) * 132 + m0]     = acc[mt][nt][1];
            zsh[n0 * 132 + m0 + 8]       = acc[mt][nt][2];
            zsh[(n0 + 1) * 132 + m0 + 8] = acc[mt][nt][3];
        }
    __syncthreads();

    int n = tid;
    float m  = __ldg(masks + t * 128 + n);
    float mn = (t < TSTEPS - 1) ? __ldg(masks + (t + 1) * 128 + n) : 0.f;
    const float* bs = (const float*)(sm + SM_BIAS) + l * 16;
    unsigned short sh[4], th[4];
    float hv[4];
#pragma unroll
    for (int u = 0; u < 4; ++u) {
        float zi = zsh[(0  + u) * 132 + n] + bs[u];
        float zf = zsh[(4  + u) * 132 + n] + bs[4 + u];
        float zg = zsh[(8  + u) * 132 + n] + bs[8 + u];
        float zo = zsh[(12 + u) * 132 + n] + bs[12 + u];
        if (zreg) {
            zi += zreg[0 * 4 + u];
            zf += zreg[1 * 4 + u];
            zg += zreg[2 * 4 + u];
            zo += zreg[3 * 4 + u];
        }
        float ii = sigm(zi), ff = sigm(zf), oo = sigm(zo);
        float gg = tanhf(zg);
        float cc = ff * (creg[u] * m) + ii * gg;
        float hh = oo * tanhf(cc);
        creg[u] = cc;
        hv[u] = hh;
        sh[u] = __half_as_ushort(__float2half_rn(hh * mn));
        if (l == 0) th[u] = __half_as_ushort(__float2half_rn(hh));
    }
    size_t base = (size_t)n * 512 + blk * 4;
    stcg2(hdst + base, sh[0] | ((uint32_t)sh[1] << 16), sh[2] | ((uint32_t)sh[3] << 16));
    if (l == 0) {
        stcg2(mdst + base, th[0] | ((uint32_t)th[1] << 16), th[2] | ((uint32_t)th[3] << 16));
    } else {
        *(float4*)(out + (size_t)t * 65536 + base) = make_float4(hv[0], hv[1], hv[2], hv[3]);
    }
    if (t == TSTEPS - 1) {
#pragma unroll
        for (int u = 0; u < 4; ++u) {
            out[OUTN + l * 131072 + n * 1024 + blk * 4 + u]       = hv[u];
            out[OUTN + l * 131072 + n * 1024 + 512 + blk * 4 + u] = creg[u];
        }
    }
    __syncthreads();   // all epilogue writes done; zsh reusable
}

// ---- main persistent kernel ------------------------------------------------
__global__ void __launch_bounds__(NTHR, 1) lstm_tc(
    const float* __restrict__ hxs, const float* __restrict__ masks,
    const float* __restrict__ W_ih, const float* __restrict__ W_hh,
    const float* __restrict__ b_ih, const float* __restrict__ b_hh,
    float* __restrict__ out)
{
    extern __shared__ __align__(1024) char sm[];
    uint32_t smb = (uint32_t)__cvta_generic_to_shared(sm);
    int tid = threadIdx.x, blk = blockIdx.x, w = tid >> 5, lane = tid & 31;
    uint32_t abase = smb + SM_A;

    // weight conversion: l=0 recurrent only (sg 0..31), l=1 full
    unsigned short* bw = (unsigned short*)(sm + SM_W);
    for (int idx = tid; idx < 2 * 16 * 1024; idx += NTHR) {
        int l = idx >> 14, col = (idx >> 10) & 15, k = idx & 1023;
        if (l == 0 && k < 512) continue;
        int grow = (col >> 2) * 512 + blk * 4 + (col & 3);
        float wv = (k < 512)
            ? W_ih[((size_t)l * 2048 + grow) * 512 + k]
            : W_hh[((size_t)l * 2048 + grow) * 512 + (k - 512)];
        unsigned short hi, lo;
        h2split(wv, hi, lo);
        int sg = (l == 0) ? ((k - 512) >> 4) : (k >> 4);
        int kk = k & 15;
        int reg = (kk >> 3) & 1, pos = kk & 1;
        int lamd = (col & 7) * 4 + ((kk & 7) >> 1);
        int nt = col >> 3;
        int base = (((l * 2 + 0) * 64 + sg) * 2 + nt) * 128 + lamd * 4 + reg * 2 + pos;
        bw[base] = hi;
        bw[base + 64 * 2 * 128] = lo;
    }
    if (tid < 32) {
        int l = tid >> 4, c = tid & 15;
        int grow = (c >> 2) * 512 + blk * 4 + (c & 3);
        ((float*)(sm + SM_BIAS))[tid] = b_ih[l * 2048 + grow] + b_hh[l * 2048 + grow];
    }

    // init masked h state (pp=0)
    for (int idx = blk * NTHR + tid; idx < 2 * 65536; idx += NBLK * NTHR) {
        int l = idx >> 16, r = idx & 65535;
        int n = r >> 9, jj = r & 511;
        float v = hxs[(size_t)l * 131072 + n * 1024 + jj] * __ldg(masks + n);
        stcg16(&g_hst[l][0][r], __half_as_ushort(__float2half_rn(v)));
    }
    float creg[2][4];
#pragma unroll
    for (int l = 0; l < 2; ++l)
#pragma unroll
        for (int u = 0; u < 4; ++u)
            creg[l][u] = hxs[(size_t)l * 131072 + tid * 1024 + 512 + blk * 4 + u];

    grid_barrier_init();
    unsigned genA0 = g_genA, genB0 = g_genB;   // replay-safe relative bases
    const uint2* bf = (const uint2*)(sm + SM_W);

#pragma unroll 1
    for (int t = 0; t < TSTEPS; ++t) {
        int pr = t & 1, mb = t & 1;
        // ================= phase 0: A = masked h0_prev (K=512) ===============
        {
            const __half* s = g_hst[0][pr];
            // prefetch x-GEMM partials (hidden behind GEMM)
            float zreg[16];
            const float* zx = g_z0x + (size_t)t * 2048 * 128;
#pragma unroll
            for (int q = 0; q < 16; ++q)
                zreg[q] = __ldg(zx + ((size_t)((q >> 2) * 512 + blk * 4 + (q & 3))) * 128 + tid);

            float acc[2][2][4] = {};
#pragma unroll
            for (int c = 0; c < 4; ++c) { stage_w32(s, s, c, abase, w, lane); cp_commit(); }
#pragma unroll 1
            for (int i = 0; i < 8; ++i) {
                cp_wait<3>();
                chunk_mma(0, i, abase, bf, w, lane, acc);
                if (i + 4 < 8) stage_w32(s, s, i + 4, abase, w, lane);
                cp_commit();
            }
            epilogue(0, t, blk, acc, zreg,
                     g_hst[0][pr ^ 1], g_mid[mb], sm, creg[0], masks, out);
            if (tid == 0) bar_arrive(&g_cntA, &g_genA);     // after epilogue syncthreads
        }
        // ================= phase 1: A = [mid ; masked h1_prev] ===============
        {
            const __half* s0 = g_mid[mb];
            const __half* s1 = g_hst[1][pr];
            // barB(t-1): all CTAs finished writing g_hst[1][pr] — usually long done
            if (tid == 0) bar_wait(&g_genB, genB0 + (unsigned)t);
            __syncthreads();
            // stage the 4 independent h1-state chunks (8..11) while barA settles
#pragma unroll
            for (int i = 0; i < 4; ++i) { stage_w32(s0, s1, 8 + i, abase, w, lane); cp_commit(); }
            // barA(t): all CTAs finished phase-0 writes (mid ready)
            if (tid == 0) bar_wait(&g_genA, genA0 + (unsigned)(t + 1));
            __syncthreads();

            float acc[2][2][4] = {};
#pragma unroll 1
            for (int i = 0; i < 16; ++i) {
                int c = (i + 8) & 15;            // 8..15 then 0..7
                cp_wait<3>();
                chunk_mma(1, c, abase, bf, w, lane, acc);
                if (i + 4 < 16) stage_w32(s0, s1, (i + 12) & 15, abase, w, lane);
                cp_commit();
            }
            epilogue(1, t, blk, acc, nullptr,
                     g_hst[1][pr ^ 1], nullptr, sm, creg[1], masks, out);
            if (tid == 0) bar_arrive(&g_cntB, &g_genB);
        }
    }
}

// ---- x0gemm: Z0x[t] = x_t @ W_ih0^T ----------------------------------------
__global__ void __launch_bounds__(256, 1) x0gemm(const float* __restrict__ W_ih) {
    extern __shared__ __align__(1024) char sm[];
    uint32_t smb = (uint32_t)__cvta_generic_to_shared(sm);
    uint32_t abase = smb + XW_BYTES;
    int tid = threadIdx.x, w = tid >> 5, lane = tid & 31;
    int sub = lane >> 3, lrow = lane & 7;
    int bc = blockIdx.x, tg = blockIdx.y;

    unsigned short* bw = (unsigned short*)sm;
    for (int idx = tid; idx < 64 * 512; idx += 256) {
        int cidx = idx >> 9, k = idx & 511;
        int gate = cidx >> 4, up = cidx & 15;
        int grow = gate * 512 + bc * 16 + up;
        float wv = W_ih[(size_t)grow * 512 + k];
        unsigned short hi, lo;
        h2split(wv, hi, lo);
        int sg = k >> 4, kk = k & 15;
        int reg = (kk >> 3) & 1, pos = kk & 1;
        int lamd = (cidx & 7) * 4 + ((kk & 7) >> 1);
        int nt = cidx >> 3;
        int base = (sg * 8 + nt) * 128 + lamd * 4 + reg * 2 + pos;
        bw[base] = hi;
        bw[base + 32 * 8 * 128] = lo;
    }
    __syncthreads();
    const uint2* bf = (const uint2*)sm;

#pragma unroll 1
    for (int tt = 0; tt < 16; ++tt) {
        int t = tg * 16 + tt;
        const __half* xs = g_x + (size_t)t * 65536;
#pragma unroll
        for (int c = 0; c < 4; ++c) { stage_w16(xs, c, abase, w, lane); cp_commit(); }

        float acc[8][4] = {};
#pragma unroll 1
        for (int i = 0; i < 8; ++i) {
            cp_wait<3>();
            uint32_t ab = abase + (i & 3) * 16384;
#pragma unroll
            for (int ks = 0; ks < 4; ++ks) {
                uint32_t Ah[4];
                int r = w * 16 + ((sub & 1) << 3) + lrow;
                uint32_t aoff = r * 128 + (((2 * ks + (sub >> 1)) ^ (r & 7)) << 4);
                ldm4(Ah, ab + aoff);
                int sg = i * 4 + ks;
#pragma unroll
                for (int nt = 0; nt < 8; ++nt) {
                    uint2 Bh = bf[(sg * 8 + nt) * 32 + lane];
                    uint2 Bl = bf[((32 + sg) * 8 + nt) * 32 + lane];
                    mma(acc[nt], Ah, Bh.x, Bh.y);
                    mma(acc[nt], Ah, Bl.x, Bl.y);
                }
            }
            if (i + 4 < 8) stage_w16(xs, i + 4, abase, w, lane);
            cp_commit();
        }

        float* Z = g_z0x + (size_t)t * 2048 * 128;
        int m0 = w * 16 + (lane >> 2);
#pragma unroll
        for (int nt = 0; nt < 8; ++nt) {
            int c0 = nt * 8 + (lane & 3) * 2, c1 = c0 + 1;
            int cg0 = (c0 >> 4) * 512 + bc * 16 + (c0 & 15);
            int cg1 = (c1 >> 4) * 512 + bc * 16 + (c1 & 15);
            __stcg(Z + (size_t)cg0 * 128 + m0,     acc[nt][0]);
            __stcg(Z + (size_t)cg1 * 128 + m0,     acc[nt][1]);
            __stcg(Z + (size_t)cg0 * 128 + m0 + 8, acc[nt][2]);
            __stcg(Z + (size_t)cg1 * 128 + m0 + 8, acc[nt][3]);
        }
    }
}

// ---- x -> fp16 -------------------------------------------------------------
__global__ void __launch_bounds__(256) xconv(const float* __restrict__ x) {
    size_t i = (size_t)blockIdx.x * 256 + threadIdx.x;
    if (i >= (size_t)OUTN / 4) return;
    float4 v = __ldg(((const float4*)x) + i);
    unsigned short h0 = __half_as_ushort(__float2half_rn(v.x));
    unsigned short h1 = __half_as_ushort(__float2half_rn(v.y));
    unsigned short h2 = __half_as_ushort(__float2half_rn(v.z));
    unsigned short h3 = __half_as_ushort(__float2half_rn(v.w));
    *(uint2*)(g_x + i * 4) = make_uint2(h0 | ((uint32_t)h1 << 16),
                                        h2 | ((uint32_t)h3 << 16));
}

// ---- LayerNorm -------------------------------------------------------------
__global__ void __launch_bounds__(256) ln_kernel(float* __restrict__ out,
                                                 const float* __restrict__ gamma,
                                                 const float* __restrict__ beta)
{
    int lane = threadIdx.x & 31;
    int row  = blockIdx.x * 8 + (threadIdx.x >> 5);
    float* p = out + (size_t)row * 512;
    float4 v[4];
    float s = 0.f, sq = 0.f;
#pragma unroll
    for (int k = 0; k < 4; ++k) {
        v[k] = ((const float4*)p)[(k << 5) + lane];
        s += v[k].x + v[k].y + v[k].z + v[k].w;
        sq = fmaf(v[k].x, v[k].x, sq); sq = fmaf(v[k].y, v[k].y, sq);
        sq = fmaf(v[k].z, v[k].z, sq); sq = fmaf(v[k].w, v[k].w, sq);
    }
#pragma unroll
    for (int o = 16; o; o >>= 1) {
        s  += __shfl_xor_sync(0xffffffffu, s,  o);
        sq += __shfl_xor_sync(0xffffffffu, sq, o);
    }
    float mean = s * (1.0f / 512.0f);
    float inv  = rsqrtf(sq * (1.0f / 512.0f) - mean * mean + 1e-5f);
#pragma unroll
    for (int k = 0; k < 4; ++k) {
        float4 gm = ((const float4*)gamma)[(k << 5) + lane];
        float4 bt = ((const float4*)beta)[(k << 5) + lane];
        float4 r;
        r.x = (v[k].x - mean) * inv * gm.x + bt.x;
        r.y = (v[k].y - mean) * inv * gm.y + bt.y;
        r.z = (v[k].z - mean) * inv * gm.z + bt.z;
        r.w = (v[k].w - mean) * inv * gm.w + bt.w;
        ((float4*)p)[(k << 5) + lane] = r;
    }
}

// ---------------------------------------------------------------------------
extern "C" void kernel_launch(void* const* d_in, const int* in_sizes, int n_in,
                              void* d_out, int out_size) {
    const float* x     = (const float*)d_in[0];
    const float* hxs   = (const float*)d_in[1];
    const float* masks = (const float*)d_in[2];
    const float* W_ih  = (const float*)d_in[3];
    const float* W_hh  = (const float*)d_in[4];
    const float* b_ih  = (const float*)d_in[5];
    const float* b_hh  = (const float*)d_in[6];
    const float* gamma = (const float*)d_in[7];
    const float* beta  = (const float*)d_in[8];
    float* out = (float*)d_out;

    cudaFuncSetAttribute(lstm_tc, cudaFuncAttributeMaxDynamicSharedMemorySize, SM_TOT);
    cudaFuncSetAttribute(x0gemm,  cudaFuncAttributeMaxDynamicSharedMemorySize, X0_TOT);

    xconv<<<(OUTN / 4 + 255) / 256, 256>>>(x);
    x0gemm<<<dim3(32, 32), 256, X0_TOT>>>(W_ih);
    lstm_tc<<<NBLK, NTHR, SM_TOT>>>(hxs, masks, W_ih, W_hh, b_ih, b_hh, out);
    ln_kernel<<<65536 / 8, 256>>>(out, gamma, beta);
}

// round 9
// speedup vs baseline: 1.2524x; 1.2524x over previous
#include <cuda_runtime.h>
#include <cuda_fp16.h>
#include <cstdint>

#define NBLK   128
#define GRP    64
#define NTHR   128
#define TSTEPS 512
#define OUTN   (512*128*512)

// ---- smem byte offsets -----------------------------------------------------
#define SM_BIAS 0          // 32 f32
#define SM_ZSH  128        // 32*132*4 = 16896
#define SM_W    17024      // B frags: [half][64 sg][4 nt][32 lane]*8B = 131072
#define SM_A    148096     // 4 bufs * 16KB = 65536
#define SM_TOT  213632

// ---- x0-free persistent state ----------------------------------------------
__device__ __align__(16) __half g_x[(size_t)TSTEPS*128*512];
__device__ __align__(16) __half g_hst[2][2][128*512];   // [layer][pingpong]
__device__ __align__(16) __half g_mid[2][128*512];      // [pingpong]
__device__ unsigned g_bar_count;
__device__ volatile unsigned g_bar_gen;
__device__ unsigned g_cntM, g_cntL1;
__device__ volatile unsigned g_genM, g_genL1;

// ---- reset kernel (graph-replay-safe absolute flags) -----------------------
__global__ void reset_flags() {
    g_bar_count = 0; g_bar_gen = 0;
    g_cntM = 0; g_cntL1 = 0; g_genM = 0; g_genL1 = 0;
}

// ---- full 128-CTA barrier (used once after init) ---------------------------
__device__ __forceinline__ void grid_barrier_full() {
    __syncthreads();
    if (threadIdx.x == 0) {
        __threadfence();
        unsigned gen = g_bar_gen;
        if (atomicAdd(&g_bar_count, 1u) == NBLK - 1) {
            g_bar_count = 0;
            __threadfence();
            g_bar_gen = gen + 1;
        } else {
            while (g_bar_gen == gen) { __nanosleep(20); }
        }
        __threadfence();
    }
    __syncthreads();
}

// ---- group barrier ops (tid0-only) -----------------------------------------
__device__ __forceinline__ void grp_arrive(unsigned* cnt, volatile unsigned* gen) {
    __threadfence();
    if (atomicAdd(cnt, 1u) == GRP - 1) {
        *cnt = 0;
        __threadfence();
        *gen = *gen + 1;
    }
}
__device__ __forceinline__ void grp_wait(volatile unsigned* gen, unsigned target) {
    while ((int)(*gen - target) < 0) { __nanosleep(20); }
    __threadfence();
}

// ---- asm helpers -----------------------------------------------------------
__device__ __forceinline__ void cp16(uint32_t s, const void* g) {
    asm volatile("cp.async.cg.shared.global [%0], [%1], 16;" :: "r"(s), "l"(g));
}
__device__ __forceinline__ void cp_commit() { asm volatile("cp.async.commit_group;"); }
template<int N> __device__ __forceinline__ void cp_wait() {
    asm volatile("cp.async.wait_group %0;" :: "n"(N));
}
__device__ __forceinline__ void ldm4(uint32_t (&a)[4], uint32_t addr) {
    asm volatile("ldmatrix.sync.aligned.m8n8.x4.shared.b16 {%0,%1,%2,%3}, [%4];"
                 : "=r"(a[0]), "=r"(a[1]), "=r"(a[2]), "=r"(a[3]) : "r"(addr));
}
__device__ __forceinline__ void mma(float (&d)[4], const uint32_t (&a)[4],
                                    uint32_t b0, uint32_t b1) {
    asm volatile("mma.sync.aligned.m16n8k16.row.col.f32.f16.f16.f32 "
        "{%0,%1,%2,%3}, {%4,%5,%6,%7}, {%8,%9}, {%0,%1,%2,%3};"
        : "+f"(d[0]), "+f"(d[1]), "+f"(d[2]), "+f"(d[3])
        : "r"(a[0]), "r"(a[1]), "r"(a[2]), "r"(a[3]), "r"(b0), "r"(b1));
}
__device__ __forceinline__ void stcg4v(void* p, uint32_t a, uint32_t b,
                                       uint32_t c, uint32_t d) {
    asm volatile("st.global.cg.v4.b32 [%0], {%1,%2,%3,%4};"
                 :: "l"(p), "r"(a), "r"(b), "r"(c), "r"(d));
}
__device__ __forceinline__ void stcg16(void* p, unsigned short v) {
    asm volatile("st.global.cg.u16 [%0], %1;" :: "l"(p), "h"(v));
}

__device__ __forceinline__ float sigm(float x) { return 1.0f / (1.0f + __expf(-x)); }

__device__ __forceinline__ void h2split(float v, unsigned short& hi, unsigned short& lo) {
    __half h = __float2half_rn(v);
    float r = v - __half2float(h);
    __half l2 = __float2half_rn(r);
    hi = __half_as_ushort(h);
    lo = __half_as_ushort(l2);
}

// ---- A staging: warp w stages its 32-row band of chunk c -------------------
__device__ __forceinline__ void stage32(const __half* src, int c,
                                        uint32_t abase, int w, int lane) {
    int coff = (c & 7) << 6;
    uint32_t dst = abase + (c & 3) * 16384;
    int rq = lane >> 3, cq = lane & 7;
#pragma unroll
    for (int jj = 0; jj < 8; ++jj) {
        int row = w * 32 + jj * 4 + rq;
        uint32_t d = dst + row * 128 + ((cq ^ (row & 7)) << 4);
        cp16(d, src + (size_t)row * 512 + coff + cq * 8);
    }
}

// ---- per-chunk GEMM: 4 ks x 4 nt x 2 mt x 2 products = 64 HMMA -------------
__device__ __forceinline__ void chunk_mma(int c, uint32_t abase, const uint2* bf,
                                          int w, int lane, float (&acc)[2][4][4]) {
    int sub = lane >> 3, lrow = lane & 7;
    uint32_t ab = abase + (c & 3) * 16384;
#pragma unroll
    for (int ks = 0; ks < 4; ++ks) {
        uint32_t Ah[2][4];
#pragma unroll
        for (int mt = 0; mt < 2; ++mt) {
            int r = w * 32 + mt * 16 + ((sub & 1) << 3) + lrow;
            uint32_t aoff = r * 128 + (((2 * ks + (sub >> 1)) ^ (r & 7)) << 4);
            ldm4(Ah[mt], ab + aoff);
        }
        int sg = c * 4 + ks;
#pragma unroll
        for (int nt = 0; nt < 4; ++nt) {
            uint2 Bh = bf[((0 * 64 + sg) * 4 + nt) * 32 + lane];
            uint2 Bl = bf[((1 * 64 + sg) * 4 + nt) * 32 + lane];
#pragma unroll
            for (int mt = 0; mt < 2; ++mt) {
                mma(acc[mt][nt], Ah[mt], Bh.x, Bh.y);
                mma(acc[mt][nt], Ah[mt], Bl.x, Bl.y);
            }
        }
    }
}

// ---- 8-chunk pipelined half ------------------------------------------------
__device__ __forceinline__ void run_half(const __half* src, int cbase,
                                         uint32_t abase, const uint2* bf,
                                         int w, int lane, float (&acc)[2][4][4]) {
#pragma unroll
    for (int c = 0; c < 4; ++c) { stage32(src, cbase + c, abase, w, lane); cp_commit(); }
#pragma unroll 1
    for (int i = 0; i < 8; ++i) {
        cp_wait<3>();
        chunk_mma(cbase + i, abase, bf, w, lane, acc);
        if (i < 4) stage32(src, cbase + i + 4, abase, w, lane);
        cp_commit();
    }
}

// ---- main persistent kernel ------------------------------------------------
__global__ void __launch_bounds__(NTHR, 1) lstm_tc(
    const float* __restrict__ hxs, const float* __restrict__ masks,
    const float* __restrict__ W_ih, const float* __restrict__ W_hh,
    const float* __restrict__ b_ih, const float* __restrict__ b_hh,
    float* __restrict__ out)
{
    extern __shared__ __align__(1024) char sm[];
    uint32_t smb = (uint32_t)__cvta_generic_to_shared(sm);
    int tid = threadIdx.x, blk = blockIdx.x, w = tid >> 5, lane = tid & 31;
    int isL0 = (blk < GRP);
    int g = isL0 ? blk : (blk - GRP);
    int l = isL0 ? 0 : 1;
    uint32_t abase = smb + SM_A;

    // ---- weight conversion: this CTA's 32 gate cols, K=1024, fp16 hi/lo ----
    unsigned short* bw = (unsigned short*)(sm + SM_W);
    for (int idx = tid; idx < 32 * 1024; idx += NTHR) {
        int col = idx >> 10, k = idx & 1023;
        int grow = (col >> 3) * 512 + g * 8 + (col & 7);
        float wv = (k < 512)
            ? W_ih[((size_t)l * 2048 + grow) * 512 + k]
            : W_hh[((size_t)l * 2048 + grow) * 512 + (k - 512)];
        unsigned short hi, lo;
        h2split(wv, hi, lo);
        int sg = k >> 4, kk = k & 15;
        int reg = (kk >> 3) & 1, pos = kk & 1;
        int lamd = (col & 7) * 4 + ((kk & 7) >> 1);
        int nt = col >> 3;
        int base = ((0 * 64 + sg) * 4 + nt) * 128 + lamd * 4 + reg * 2 + pos;
        bw[base] = hi;
        bw[base + 64 * 4 * 128] = lo;
    }
    if (tid < 32) {
        int c = tid;
        int grow = (c >> 3) * 512 + g * 8 + (c & 7);
        ((float*)(sm + SM_BIAS))[c] = b_ih[l * 2048 + grow] + b_hh[l * 2048 + grow];
    }

    // ---- init masked h state (pp=0): grid-strided over both layers ---------
    for (int idx = blk * NTHR + tid; idx < 2 * 65536; idx += NBLK * NTHR) {
        int ll = idx >> 16, r = idx & 65535;
        int n = r >> 9, jj = r & 511;
        float v = hxs[(size_t)ll * 131072 + n * 1024 + jj] * __ldg(masks + n);
        stcg16(&g_hst[ll][0][r], __half_as_ushort(__float2half_rn(v)));
    }
    // c-state: thread n = tid owns 8 units of this CTA's layer
    float creg[8];
#pragma unroll
    for (int u = 0; u < 8; ++u)
        creg[u] = hxs[(size_t)l * 131072 + tid * 1024 + 512 + g * 8 + u];

    grid_barrier_full();
    const uint2* bf = (const uint2*)(sm + SM_W);
    float* zsh = (float*)(sm + SM_ZSH);
    const float* bs = (const float*)(sm + SM_BIAS);

#pragma unroll 1
    for (int t = 0; t < TSTEPS; ++t) {
        int pr = t & 1, pw = pr ^ 1, mb = t & 1;
        float acc[2][4][4] = {};

        if (isL0) {
            // half A: x_t chunks 0-7 (no dependency)
            run_half(g_x + (size_t)t * 65536, 0, abase, bf, w, lane, acc);
            // wait: own group's h0(t-1) done; L1 freed mid(t) buffer
            if (tid == 0) {
                grp_wait(&g_genM, (unsigned)t);
                if (t >= 2) grp_wait(&g_genL1, (unsigned)(t - 1));
            }
            __syncthreads();
            // half B: recurrent h0(t-1) chunks 8-15
            run_half(g_hst[0][pr], 8, abase, bf, w, lane, acc);
        } else {
            // wait: own group's h1(t-1) done
            if (tid == 0) grp_wait(&g_genL1, (unsigned)t);
            __syncthreads();
            // half A: recurrent h1(t-1) chunks 8-15
            run_half(g_hst[1][pr], 8, abase, bf, w, lane, acc);
            // wait: mid(t) ready (all 64 L0 CTAs finished step t)
            if (tid == 0) grp_wait(&g_genM, (unsigned)(t + 1));
            __syncthreads();
            // half B: mid chunks 0-7
            run_half(g_mid[mb], 0, abase, bf, w, lane, acc);
        }

        // ---- epilogue: z transpose -> gates -> state writes -----------------
#pragma unroll
        for (int mt = 0; mt < 2; ++mt)
#pragma unroll
            for (int nt = 0; nt < 4; ++nt) {
                int m0 = w * 32 + mt * 16 + (lane >> 2);
                int n0 = nt * 8 + (lane & 3) * 2;
                zsh[n0 * 132 + m0]           = acc[mt][nt][0];
                zsh[(n0 + 1) * 132 + m0]     = acc[mt][nt][1];
                zsh[n0 * 132 + m0 + 8]       = acc[mt][nt][2];
                zsh[(n0 + 1) * 132 + m0 + 8] = acc[mt][nt][3];
            }
        __syncthreads();

        int n = tid;
        float m  = __ldg(masks + t * 128 + n);
        float mn = (t < TSTEPS - 1) ? __ldg(masks + (t + 1) * 128 + n) : 0.f;
        unsigned short sh[8], th[8];
        float hv[8];
#pragma unroll
        for (int u = 0; u < 8; ++u) {
            float zi = zsh[(0  + u) * 132 + n] + bs[u];
            float zf = zsh[(8  + u) * 132 + n] + bs[8 + u];
            float zg = zsh[(16 + u) * 132 + n] + bs[16 + u];
            float zo = zsh[(24 + u) * 132 + n] + bs[24 + u];
            float ii = sigm(zi), ff = sigm(zf), oo = sigm(zo);
            float gg = tanhf(zg);
            float cc = ff * (creg[u] * m) + ii * gg;
            float hh = oo * tanhf(cc);
            creg[u] = cc;
            hv[u] = hh;
            sh[u] = __half_as_ushort(__float2half_rn(hh * mn));
            if (isL0) th[u] = __half_as_ushort(__float2half_rn(hh));
        }
        size_t base = (size_t)n * 512 + g * 8;
        stcg4v(&g_hst[l][pw][base],
               sh[0] | ((uint32_t)sh[1] << 16), sh[2] | ((uint32_t)sh[3] << 16),
               sh[4] | ((uint32_t)sh[5] << 16), sh[6] | ((uint32_t)sh[7] << 16));
        if (isL0) {
            stcg4v(&g_mid[mb][base],
                   th[0] | ((uint32_t)th[1] << 16), th[2] | ((uint32_t)th[3] << 16),
                   th[4] | ((uint32_t)th[5] << 16), th[6] | ((uint32_t)th[7] << 16));
        } else {
            float* op = out + (size_t)t * 65536 + base;
            *(float4*)op       = make_float4(hv[0], hv[1], hv[2], hv[3]);
            *(float4*)(op + 4) = make_float4(hv[4], hv[5], hv[6], hv[7]);
        }
        if (t == TSTEPS - 1) {
#pragma unroll
            for (int u = 0; u < 8; ++u) {
                out[OUTN + l * 131072 + n * 1024 + g * 8 + u]       = hv[u];
                out[OUTN + l * 131072 + n * 1024 + 512 + g * 8 + u] = creg[u];
            }
        }
        __syncthreads();   // zsh reusable; all state writes issued

        if (tid == 0) {
            if (isL0) grp_arrive(&g_cntM, &g_genM);
            else      grp_arrive(&g_cntL1, &g_genL1);
        }
    }
}

// ---- x -> fp16 -------------------------------------------------------------
__global__ void __launch_bounds__(256) xconv(const float* __restrict__ x) {
    size_t i = (size_t)blockIdx.x * 256 + threadIdx.x;
    if (i >= (size_t)OUTN / 4) return;
    float4 v = __ldg(((const float4*)x) + i);
    unsigned short h0 = __half_as_ushort(__float2half_rn(v.x));
    unsigned short h1 = __half_as_ushort(__float2half_rn(v.y));
    unsigned short h2 = __half_as_ushort(__float2half_rn(v.z));
    unsigned short h3 = __half_as_ushort(__float2half_rn(v.w));
    *(uint2*)(g_x + i * 4) = make_uint2(h0 | ((uint32_t)h1 << 16),
                                        h2 | ((uint32_t)h3 << 16));
}

// ---- LayerNorm -------------------------------------------------------------
__global__ void __launch_bounds__(256) ln_kernel(float* __restrict__ out,
                                                 const float* __restrict__ gamma,
                                                 const float* __restrict__ beta)
{
    int lane = threadIdx.x & 31;
    int row  = blockIdx.x * 8 + (threadIdx.x >> 5);
    float* p = out + (size_t)row * 512;
    float4 v[4];
    float s = 0.f, sq = 0.f;
#pragma unroll
    for (int k = 0; k < 4; ++k) {
        v[k] = ((const float4*)p)[(k << 5) + lane];
        s += v[k].x + v[k].y + v[k].z + v[k].w;
        sq = fmaf(v[k].x, v[k].x, sq); sq = fmaf(v[k].y, v[k].y, sq);
        sq = fmaf(v[k].z, v[k].z, sq); sq = fmaf(v[k].w, v[k].w, sq);
    }
#pragma unroll
    for (int o = 16; o; o >>= 1) {
        s  += __shfl_xor_sync(0xffffffffu, s,  o);
        sq += __shfl_xor_sync(0xffffffffu, sq, o);
    }
    float mean = s * (1.0f / 512.0f);
    float inv  = rsqrtf(sq * (1.0f / 512.0f) - mean * mean + 1e-5f);
#pragma unroll
    for (int k = 0; k < 4; ++k) {
        float4 gm = ((const float4*)gamma)[(k << 5) + lane];
        float4 bt = ((const float4*)beta)[(k << 5) + lane];
        float4 r;
        r.x = (v[k].x - mean) * inv * gm.x + bt.x;
        r.y = (v[k].y - mean) * inv * gm.y + bt.y;
        r.z = (v[k].z - mean) * inv * gm.z + bt.z;
        r.w = (v[k].w - mean) * inv * gm.w + bt.w;
        ((float4*)p)[(k << 5) + lane] = r;
    }
}

// ---------------------------------------------------------------------------
extern "C" void kernel_launch(void* const* d_in, const int* in_sizes, int n_in,
                              void* d_out, int out_size) {
    const float* x     = (const float*)d_in[0];
    const float* hxs   = (const float*)d_in[1];
    const float* masks = (const float*)d_in[2];
    const float* W_ih  = (const float*)d_in[3];
    const float* W_hh  = (const float*)d_in[4];
    const float* b_ih  = (const float*)d_in[5];
    const float* b_hh  = (const float*)d_in[6];
    const float* gamma = (const float*)d_in[7];
    const float* beta  = (const float*)d_in[8];
    float* out = (float*)d_out;

    cudaFuncSetAttribute(lstm_tc, cudaFuncAttributeMaxDynamicSharedMemorySize, SM_TOT);

    reset_flags<<<1, 1>>>();
    xconv<<<(OUTN / 4 + 255) / 256, 256>>>(x);
    lstm_tc<<<NBLK, NTHR, SM_TOT>>>(hxs, masks, W_ih, W_hh, b_ih, b_hh, out);
    ln_kernel<<<65536 / 8, 256>>>(out, gamma, beta);
}